// round 15
// baseline (speedup 1.0000x reference)
#include <cuda_runtime.h>

// Problem constants (match reference)
#define N_ATOMS   245760
#define N_PAIRS   16777216
#define N_MOLS    4096
#define KE_CONST  138.96f

#define THREADS   256
#define BLOCKS    1184   // 8 blocks/SM x 148 SMs — same 64 warps/SM, finer tail

// ---------------------------------------------------------------------------
// Per-pair work: gathers + chi(d) + SMEM scatter (byte-identical math to R14)
// ---------------------------------------------------------------------------
__device__ __forceinline__ void process_pair(
    const float* __restrict__ q,
    int i, int j, float d, int s,
    float* __restrict__ acc)
{
    // Gather charges (random access; L1/L2 default caching)
    float qi = __ldg(q + i);
    float qj = __ldg(q + j);

    // phi(2d) = 1 - 6u^5 + 15u^4 - 10u^3 with u = 2d, valid for u < 1
    float u  = 2.0f * d;
    float u2 = u * u;
    float u3 = u2 * u;
    float inner = fmaf(-6.0f, u2, fmaf(15.0f, u, -10.0f));
    float phi   = fmaf(u3, inner, 1.0f);
    phi = (u < 1.0f) ? phi : 0.0f;

    // chi = phi / sqrt(d^2+1) + (1-phi)/d  ==  rd + phi*(rs - rd)
    float rs = rsqrtf(fmaf(d, d, 1.0f));     // MUFU.RSQ
    float rd = __fdividef(1.0f, d);          // MUFU.RCP (approx)
    float chi = fmaf(phi, rs - rd, rd);

    if (i < j) {
        atomicAdd(&acc[s], qi * qj * chi);
    }
}

// ---------------------------------------------------------------------------
// Single fused kernel (R14 structure): block 0 prologue initializes out;
// hot loop byte-identical; 256-thread CTAs for finer end-of-kernel tail.
// ---------------------------------------------------------------------------
__global__ __launch_bounds__(THREADS)
void coulomb_pairs_kernel(const float* __restrict__ q,
                          const int*   __restrict__ idx_i,
                          const int*   __restrict__ idx_j,
                          const float* __restrict__ d_ij,
                          const int*   __restrict__ seg,
                          const float* __restrict__ pse,
                          float*       __restrict__ out)
{
    __shared__ float acc[N_MOLS];   // 16 KB per-block private histogram

    // Block 0 prologue: out = pse * KE (coalesced STG; single wave + ~127us
    // main loop gives >100x visibility margin before any flush atomic).
    if (blockIdx.x == 0) {
        for (int m = threadIdx.x; m < N_MOLS; m += THREADS)
            out[m] = pse[m] * KE_CONST;
    }

    for (int m = threadIdx.x; m < N_MOLS; m += THREADS)
        acc[m] = 0.0f;
    __syncthreads();

    const int nquads = N_PAIRS / 4;
    const int stride = gridDim.x * THREADS;

    for (int t = blockIdx.x * THREADS + threadIdx.x; t < nquads; t += stride) {
        // Streaming loads, evict-first so the charge table keeps L1
        int4   vi = __ldcs(reinterpret_cast<const int4*>(idx_i) + t);
        int4   vj = __ldcs(reinterpret_cast<const int4*>(idx_j) + t);
        float4 vd = __ldcs(reinterpret_cast<const float4*>(d_ij) + t);
        int4   vs = __ldcs(reinterpret_cast<const int4*>(seg)   + t);

        process_pair(q, vi.x, vj.x, vd.x, vs.x, acc);
        process_pair(q, vi.y, vj.y, vd.y, vs.y, acc);
        process_pair(q, vi.z, vj.z, vd.z, vs.z, acc);
        process_pair(q, vi.w, vj.w, vd.w, vs.w, acc);
    }

    __syncthreads();

    // Flush block-private histogram (out already holds pse*KE; staggered
    // CTA completion keeps these L2 atomics fully overlapped — R11-verified).
    for (int m = threadIdx.x; m < N_MOLS; m += THREADS) {
        float v = acc[m];
        if (v != 0.0f)
            atomicAdd(&out[m], v * KE_CONST);
    }
}

// ---------------------------------------------------------------------------
// Launch — single kernel, single wave
// ---------------------------------------------------------------------------
extern "C" void kernel_launch(void* const* d_in, const int* in_sizes, int n_in,
                              void* d_out, int out_size) {
    const float* q    = (const float*)d_in[0];           // per_atom_charge [N_ATOMS]
    const int*   pidx = (const int*)  d_in[1];           // pair_indices [2, N_PAIRS]
    const float* dij  = (const float*)d_in[2];           // d_ij [N_PAIRS]
    const int*   seg  = (const int*)  d_in[3];           // atomic_subsystem_indices [N_PAIRS]
    const float* pse  = (const float*)d_in[4];           // per_system_energy [N_MOLS]
    float* out = (float*)d_out;

    const int* idx_i = pidx;
    const int* idx_j = pidx + N_PAIRS;

    coulomb_pairs_kernel<<<BLOCKS, THREADS>>>(q, idx_i, idx_j, dij, seg, pse, out);
}

// round 16
// speedup vs baseline: 1.1124x; 1.1124x over previous
#include <cuda_runtime.h>

// Problem constants (match reference)
#define N_ATOMS   245760
#define N_PAIRS   16777216
#define N_MOLS    4096
#define KE_CONST  138.96f

// ---------------------------------------------------------------------------
// Per-pair work: gathers + chi(d) + SMEM scatter
// ---------------------------------------------------------------------------
__device__ __forceinline__ void process_pair(
    const float* __restrict__ q,
    int i, int j, float d, int s,
    float* __restrict__ acc)
{
    // Gather charges (random access; L1/L2 default caching)
    float qi = __ldg(q + i);
    float qj = __ldg(q + j);

    // phi(2d) = 1 - 6u^5 + 15u^4 - 10u^3 with u = 2d, valid for u < 1
    float u  = 2.0f * d;
    float u2 = u * u;
    float u3 = u2 * u;
    float inner = fmaf(-6.0f, u2, fmaf(15.0f, u, -10.0f));
    float phi   = fmaf(u3, inner, 1.0f);
    phi = (u < 1.0f) ? phi : 0.0f;

    // chi = phi / sqrt(d^2+1) + (1-phi)/d  ==  rd + phi*(rs - rd)
    float rs = rsqrtf(fmaf(d, d, 1.0f));     // MUFU.RSQ
    float rd = __fdividef(1.0f, d);          // MUFU.RCP (approx)
    float chi = fmaf(phi, rs - rd, rd);

    if (i < j) {
        atomicAdd(&acc[s], qi * qj * chi);
    }
}

// ---------------------------------------------------------------------------
// Single fused kernel: block 0 initializes out in its prologue (single wave
// + ~127us main loop gives a >100x timing margin before any flush atomic);
// hot loop and epilogue are the measured-best R1 structure.
// ---------------------------------------------------------------------------
__global__ __launch_bounds__(512)
void coulomb_pairs_kernel(const float* __restrict__ q,
                          const int*   __restrict__ idx_i,
                          const int*   __restrict__ idx_j,
                          const float* __restrict__ d_ij,
                          const int*   __restrict__ seg,
                          const float* __restrict__ pse,
                          float*       __restrict__ out)
{
    __shared__ float acc[N_MOLS];   // 16 KB per-block private histogram

    // Block 0 prologue: out = pse * KE (8 coalesced STG iterations, <1us;
    // global stores are write-through to L2 where the flush atomics operate).
    if (blockIdx.x == 0) {
        for (int m = threadIdx.x; m < N_MOLS; m += blockDim.x)
            out[m] = pse[m] * KE_CONST;
    }

    for (int m = threadIdx.x; m < N_MOLS; m += blockDim.x)
        acc[m] = 0.0f;
    __syncthreads();

    const int nquads = N_PAIRS / 4;
    const int stride = gridDim.x * blockDim.x;

    for (int t = blockIdx.x * blockDim.x + threadIdx.x; t < nquads; t += stride) {
        // Streaming loads, evict-first so the charge table keeps L1
        int4   vi = __ldcs(reinterpret_cast<const int4*>(idx_i) + t);
        int4   vj = __ldcs(reinterpret_cast<const int4*>(idx_j) + t);
        float4 vd = __ldcs(reinterpret_cast<const float4*>(d_ij) + t);
        int4   vs = __ldcs(reinterpret_cast<const int4*>(seg)   + t);

        process_pair(q, vi.x, vj.x, vd.x, vs.x, acc);
        process_pair(q, vi.y, vj.y, vd.y, vs.y, acc);
        process_pair(q, vi.z, vj.z, vd.z, vs.z, acc);
        process_pair(q, vi.w, vj.w, vd.w, vs.w, acc);
    }

    __syncthreads();

    // Flush block-private histogram to global (out already holds pse*KE;
    // block 0 wrote it ~127us ago — far beyond any visibility latency).
    for (int m = threadIdx.x; m < N_MOLS; m += blockDim.x) {
        float v = acc[m];
        if (v != 0.0f)
            atomicAdd(&out[m], v * KE_CONST);
    }
}

// ---------------------------------------------------------------------------
// Launch — single kernel, single wave: 4 blocks/SM x 148 SMs, 512 threads
// ---------------------------------------------------------------------------
extern "C" void kernel_launch(void* const* d_in, const int* in_sizes, int n_in,
                              void* d_out, int out_size) {
    const float* q    = (const float*)d_in[0];           // per_atom_charge [N_ATOMS]
    const int*   pidx = (const int*)  d_in[1];           // pair_indices [2, N_PAIRS]
    const float* dij  = (const float*)d_in[2];           // d_ij [N_PAIRS]
    const int*   seg  = (const int*)  d_in[3];           // atomic_subsystem_indices [N_PAIRS]
    const float* pse  = (const float*)d_in[4];           // per_system_energy [N_MOLS]
    float* out = (float*)d_out;

    const int* idx_i = pidx;
    const int* idx_j = pidx + N_PAIRS;

    const int blocks  = 592;
    const int threads = 512;
    coulomb_pairs_kernel<<<blocks, threads>>>(q, idx_i, idx_j, dij, seg, pse, out);
}

// round 17
// speedup vs baseline: 1.1127x; 1.0003x over previous
#include <cuda_runtime.h>

// Problem constants (match reference)
#define N_ATOMS   245760
#define N_PAIRS   16777216
#define N_MOLS    4096
#define KE_CONST  138.96f

// ---------------------------------------------------------------------------
// Per-pair work: gathers + chi(d) + SMEM scatter
// ---------------------------------------------------------------------------
__device__ __forceinline__ void process_pair(
    const float* __restrict__ q,
    int i, int j, float d, int s,
    float* __restrict__ acc)
{
    // Gather charges (random access; L1/L2 default caching)
    float qi = __ldg(q + i);
    float qj = __ldg(q + j);

    // phi(2d) = 1 - 6u^5 + 15u^4 - 10u^3 with u = 2d, valid for u < 1
    float u  = 2.0f * d;
    float u2 = u * u;
    float u3 = u2 * u;
    float inner = fmaf(-6.0f, u2, fmaf(15.0f, u, -10.0f));
    float phi   = fmaf(u3, inner, 1.0f);
    phi = (u < 1.0f) ? phi : 0.0f;

    // chi = phi / sqrt(d^2+1) + (1-phi)/d  ==  rd + phi*(rs - rd)
    float rs = rsqrtf(fmaf(d, d, 1.0f));     // MUFU.RSQ
    float rd = __fdividef(1.0f, d);          // MUFU.RCP (approx)
    float chi = fmaf(phi, rs - rd, rd);

    if (i < j) {
        atomicAdd(&acc[s], qi * qj * chi);
    }
}

// ---------------------------------------------------------------------------
// Single fused kernel: block 0 initializes out in its prologue (single wave
// + ~127us main loop gives a >100x timing margin before any flush atomic);
// hot loop and epilogue are the measured-best structure.
// ---------------------------------------------------------------------------
__global__ __launch_bounds__(512)
void coulomb_pairs_kernel(const float* __restrict__ q,
                          const int*   __restrict__ idx_i,
                          const int*   __restrict__ idx_j,
                          const float* __restrict__ d_ij,
                          const int*   __restrict__ seg,
                          const float* __restrict__ pse,
                          float*       __restrict__ out)
{
    __shared__ float acc[N_MOLS];   // 16 KB per-block private histogram

    // Block 0 prologue: out = pse * KE (8 coalesced STG iterations, <1us;
    // global stores are write-through to L2 where the flush atomics operate).
    if (blockIdx.x == 0) {
        for (int m = threadIdx.x; m < N_MOLS; m += blockDim.x)
            out[m] = pse[m] * KE_CONST;
    }

    for (int m = threadIdx.x; m < N_MOLS; m += blockDim.x)
        acc[m] = 0.0f;
    __syncthreads();

    const int nquads = N_PAIRS / 4;
    const int stride = gridDim.x * blockDim.x;

    for (int t = blockIdx.x * blockDim.x + threadIdx.x; t < nquads; t += stride) {
        // Streaming loads, evict-first so the charge table keeps L1
        int4   vi = __ldcs(reinterpret_cast<const int4*>(idx_i) + t);
        int4   vj = __ldcs(reinterpret_cast<const int4*>(idx_j) + t);
        float4 vd = __ldcs(reinterpret_cast<const float4*>(d_ij) + t);
        int4   vs = __ldcs(reinterpret_cast<const int4*>(seg)   + t);

        process_pair(q, vi.x, vj.x, vd.x, vs.x, acc);
        process_pair(q, vi.y, vj.y, vd.y, vs.y, acc);
        process_pair(q, vi.z, vj.z, vd.z, vs.z, acc);
        process_pair(q, vi.w, vj.w, vd.w, vs.w, acc);
    }

    __syncthreads();

    // Flush block-private histogram to global (out already holds pse*KE;
    // block 0 wrote it ~127us ago — far beyond any visibility latency).
    for (int m = threadIdx.x; m < N_MOLS; m += blockDim.x) {
        float v = acc[m];
        if (v != 0.0f)
            atomicAdd(&out[m], v * KE_CONST);
    }
}

// ---------------------------------------------------------------------------
// Launch — single kernel, single wave: 4 blocks/SM x 148 SMs, 512 threads
// ---------------------------------------------------------------------------
extern "C" void kernel_launch(void* const* d_in, const int* in_sizes, int n_in,
                              void* d_out, int out_size) {
    const float* q    = (const float*)d_in[0];           // per_atom_charge [N_ATOMS]
    const int*   pidx = (const int*)  d_in[1];           // pair_indices [2, N_PAIRS]
    const float* dij  = (const float*)d_in[2];           // d_ij [N_PAIRS]
    const int*   seg  = (const int*)  d_in[3];           // atomic_subsystem_indices [N_PAIRS]
    const float* pse  = (const float*)d_in[4];           // per_system_energy [N_MOLS]
    float* out = (float*)d_out;

    const int* idx_i = pidx;
    const int* idx_j = pidx + N_PAIRS;

    const int blocks  = 592;
    const int threads = 512;
    coulomb_pairs_kernel<<<blocks, threads>>>(q, idx_i, idx_j, dij, seg, pse, out);
}